// round 1
// baseline (speedup 1.0000x reference)
#include <cuda_runtime.h>
#include <cstddef>

// Problem dims (fixed by the reference)
#define NB     16          // batch
#define FIN    512         // input features
#define TD     512         // time
#define MR     8192        // NB*TD rows
#define HD     2048        // hidden

// ---------------- scratch (static device globals; no allocation) -------------
__device__ float g_xt[MR * FIN];       // 16 MB: x transposed to (M, F)
__device__ float g_h [(size_t)MR * HD]; // 64 MB: pre-BN GEMM output
__device__ float g_a [(size_t)MR * HD]; // 64 MB: sign activations (+-1 / 0)
__device__ float g_mu[HD];
__device__ float g_rs[HD];
__device__ float g_ps[8 * HD];         // partial sums
__device__ float g_pq[8 * HD];         // partial sums of squares

__device__ __forceinline__ float sgnf(float v) {
    return (v > 0.f) ? 1.f : ((v < 0.f) ? -1.f : 0.f);
}

// ---------------- x (N,F,T) -> xt (N*T, F) ----------------------------------
__global__ void transpose_x(const float* __restrict__ x, float* __restrict__ xt) {
    __shared__ float tile[32][33];
    int n  = blockIdx.z;
    int t0 = blockIdx.x * 32;
    int f0 = blockIdx.y * 32;
    const float* xp = x + (size_t)n * FIN * TD;
#pragma unroll
    for (int i = 0; i < 4; i++) {
        int f = f0 + threadIdx.y + i * 8;
        tile[threadIdx.y + i * 8][threadIdx.x] = xp[(size_t)f * TD + t0 + threadIdx.x];
    }
    __syncthreads();
#pragma unroll
    for (int i = 0; i < 4; i++) {
        int t = t0 + threadIdx.y + i * 8;
        xt[((size_t)n * TD + t) * FIN + f0 + threadIdx.x] = tile[threadIdx.x][threadIdx.y + i * 8];
    }
}

// ---------------- GEMM: C[m,n] = sum_k A[m,k] * sgn(W[n,k]) -----------------
// A: (M,K) row-major, W: (N,K) row-major (binarized on load).
// EPI 0: C[m,n] = acc      (C is (M,N) row-major)
// EPI 1: y[batch, n, t] = acc * scale[n]   with m = batch*TD + t  (final layer)
template <int EPI>
__global__ void __launch_bounds__(256)
gemm_bin(const float* __restrict__ A, const float* __restrict__ W,
         float* __restrict__ C, int M, int N, int K,
         const float* __restrict__ scale)
{
    const int BM = 128, BN = 128, BK = 16;
    const int LDS = BM + 4; // padded stride (floats)
    __shared__ float As[BK * LDS];
    __shared__ float Bs[BK * LDS];

    int bm = blockIdx.y * BM;
    int bn = blockIdx.x * BN;
    int tid = threadIdx.x;
    int ty = tid >> 4;          // 0..15
    int tx = tid & 15;          // 0..15

    float acc[8][8];
#pragma unroll
    for (int i = 0; i < 8; i++)
#pragma unroll
        for (int j = 0; j < 8; j++) acc[i][j] = 0.f;

    for (int k0 = 0; k0 < K; k0 += BK) {
#pragma unroll
        for (int v = 0; v < 2; v++) {
            int idx = tid * 2 + v;         // 0..511 float4 slots
            int r   = idx >> 2;            // row within tile 0..127
            int kq  = (idx & 3) * 4;       // k offset 0,4,8,12
            float4 av = *(const float4*)&A[(size_t)(bm + r) * K + k0 + kq];
            As[(kq + 0) * LDS + r] = av.x;
            As[(kq + 1) * LDS + r] = av.y;
            As[(kq + 2) * LDS + r] = av.z;
            As[(kq + 3) * LDS + r] = av.w;
            float4 wv = *(const float4*)&W[(size_t)(bn + r) * K + k0 + kq];
            Bs[(kq + 0) * LDS + r] = sgnf(wv.x);
            Bs[(kq + 1) * LDS + r] = sgnf(wv.y);
            Bs[(kq + 2) * LDS + r] = sgnf(wv.z);
            Bs[(kq + 3) * LDS + r] = sgnf(wv.w);
        }
        __syncthreads();

#pragma unroll
        for (int k = 0; k < BK; k++) {
            float a[8], b[8];
            *(float4*)(a)     = *(const float4*)&As[k * LDS + ty * 8];
            *(float4*)(a + 4) = *(const float4*)&As[k * LDS + ty * 8 + 4];
            *(float4*)(b)     = *(const float4*)&Bs[k * LDS + tx * 8];
            *(float4*)(b + 4) = *(const float4*)&Bs[k * LDS + tx * 8 + 4];
#pragma unroll
            for (int i = 0; i < 8; i++)
#pragma unroll
                for (int j = 0; j < 8; j++)
                    acc[i][j] = fmaf(a[i], b[j], acc[i][j]);
        }
        __syncthreads();
    }

    if (EPI == 0) {
#pragma unroll
        for (int i = 0; i < 8; i++) {
            int m = bm + ty * 8 + i;
            float* cp = &C[(size_t)m * N + bn + tx * 8];
            float4 v0 = make_float4(acc[i][0], acc[i][1], acc[i][2], acc[i][3]);
            float4 v1 = make_float4(acc[i][4], acc[i][5], acc[i][6], acc[i][7]);
            *(float4*)(cp)     = v0;
            *(float4*)(cp + 4) = v1;
        }
    } else {
        // final layer: m = batch*TD + t ; write y[batch, fo, t] = acc * scale[fo]
        int batch = bm / TD;
        int tbase = (bm % TD) + ty * 8;
#pragma unroll
        for (int j = 0; j < 8; j++) {
            int fo = bn + tx * 8 + j;
            float s = scale[fo];
            float* yp = &C[((size_t)batch * FIN + fo) * TD + tbase];
            float4 v0 = make_float4(acc[0][j] * s, acc[1][j] * s, acc[2][j] * s, acc[3][j] * s);
            float4 v1 = make_float4(acc[4][j] * s, acc[5][j] * s, acc[6][j] * s, acc[7][j] * s);
            *(float4*)(yp)     = v0;
            *(float4*)(yp + 4) = v1;
        }
    }
}

// ---------------- BN stats: two-stage deterministic column reduction --------
// grid (HD/32, 8), block 256 = 32 cols x 8 row-lanes. Each y-block reduces 1024 rows.
__global__ void stats_partial(const float* __restrict__ h,
                              float* __restrict__ ps, float* __restrict__ pq) {
    int c    = (threadIdx.x & 31);
    int lane = (threadIdx.x >> 5);           // 0..7
    int col  = blockIdx.x * 32 + c;
    int r0   = blockIdx.y * (MR / 8);        // 1024 rows per y-block
    float s = 0.f, sq = 0.f;
    for (int i = lane; i < MR / 8; i += 8) {
        float v = h[(size_t)(r0 + i) * HD + col];
        s += v;
        sq += v * v;
    }
    __shared__ float ss[8][33];
    __shared__ float sv[8][33];
    ss[lane][c] = s;
    sv[lane][c] = sq;
    __syncthreads();
    if (lane == 0) {
        float ts = 0.f, tq = 0.f;
#pragma unroll
        for (int l = 0; l < 8; l++) { ts += ss[l][c]; tq += sv[l][c]; }
        ps[blockIdx.y * HD + col] = ts;
        pq[blockIdx.y * HD + col] = tq;
    }
}

__global__ void stats_final(const float* __restrict__ ps, const float* __restrict__ pq,
                            float* __restrict__ mu, float* __restrict__ rs) {
    int col = blockIdx.x * 256 + threadIdx.x;
    if (col >= HD) return;
    float s = 0.f, sq = 0.f;
#pragma unroll
    for (int p = 0; p < 8; p++) { s += ps[p * HD + col]; sq += pq[p * HD + col]; }
    float m = s * (1.f / MR);
    float var = sq * (1.f / MR) - m * m;
    if (var < 0.f) var = 0.f;
    mu[col] = m;
    rs[col] = rsqrtf(var + 1e-5f);
}

// ---------------- sign activation: a = sign(g*(h-mu)*rs + b) ----------------
__global__ void sign_act(const float* __restrict__ h,
                         const float* __restrict__ mu, const float* __restrict__ rs,
                         const float* __restrict__ g, const float* __restrict__ b,
                         float* __restrict__ a) {
    size_t i4 = (size_t)blockIdx.x * blockDim.x + threadIdx.x;  // float4 index
    size_t e0 = i4 * 4;
    if (e0 >= (size_t)MR * HD) return;
    int j = (int)(e0 % HD);   // HD multiple of 4 -> all 4 lanes in same row-stripe
    float4 hv = *(const float4*)&h[e0];
    float4 ov;
    ov.x = sgnf(g[j + 0] * (hv.x - mu[j + 0]) * rs[j + 0] + b[j + 0]);
    ov.y = sgnf(g[j + 1] * (hv.y - mu[j + 1]) * rs[j + 1] + b[j + 1]);
    ov.z = sgnf(g[j + 2] * (hv.z - mu[j + 2]) * rs[j + 2] + b[j + 2]);
    ov.w = sgnf(g[j + 3] * (hv.w - mu[j + 3]) * rs[j + 3] + b[j + 3]);
    *(float4*)&a[e0] = ov;
}

// ---------------- host orchestration ----------------------------------------
extern "C" void kernel_launch(void* const* d_in, const int* in_sizes, int n_in,
                              void* d_out, int out_size) {
    const float* x     = (const float*)d_in[0];
    // d_in[1] = conv_w : dead computation in the reference, skipped
    const float* W1    = (const float*)d_in[2];
    const float* g1    = (const float*)d_in[3];
    const float* b1    = (const float*)d_in[4];
    const float* W2    = (const float*)d_in[5];
    const float* g2    = (const float*)d_in[6];
    const float* b2    = (const float*)d_in[7];
    const float* W3    = (const float*)d_in[8];
    const float* g3    = (const float*)d_in[9];
    const float* b3    = (const float*)d_in[10];
    const float* W4    = (const float*)d_in[11];
    const float* scale = (const float*)d_in[12];
    float* y = (float*)d_out;

    float *xt, *h, *a, *mu, *rs, *ps, *pq;
    cudaGetSymbolAddress((void**)&xt, g_xt);
    cudaGetSymbolAddress((void**)&h,  g_h);
    cudaGetSymbolAddress((void**)&a,  g_a);
    cudaGetSymbolAddress((void**)&mu, g_mu);
    cudaGetSymbolAddress((void**)&rs, g_rs);
    cudaGetSymbolAddress((void**)&ps, g_ps);
    cudaGetSymbolAddress((void**)&pq, g_pq);

    // 1) transpose x -> (M, F)
    {
        dim3 grid(TD / 32, FIN / 32, NB), blk(32, 8);
        transpose_x<<<grid, blk>>>(x, xt);
    }

    dim3 blk(256);
    dim3 gridStats(HD / 32, 8);
    dim3 gridSign((unsigned)(((size_t)MR * HD / 4 + 255) / 256));

    // 2) layer 1: h = xt @ sgn(W1)^T   (M=8192, N=2048, K=512)
    gemm_bin<0><<<dim3(HD / 128, MR / 128), blk>>>(xt, W1, h, MR, HD, FIN, nullptr);
    stats_partial<<<gridStats, blk>>>(h, ps, pq);
    stats_final<<<dim3(HD / 256), blk>>>(ps, pq, mu, rs);
    sign_act<<<gridSign, blk>>>(h, mu, rs, g1, b1, a);

    // 3) layer 2: h = a @ sgn(W2)^T    (K=2048)
    gemm_bin<0><<<dim3(HD / 128, MR / 128), blk>>>(a, W2, h, MR, HD, HD, nullptr);
    stats_partial<<<gridStats, blk>>>(h, ps, pq);
    stats_final<<<dim3(HD / 256), blk>>>(ps, pq, mu, rs);
    sign_act<<<gridSign, blk>>>(h, mu, rs, g2, b2, a);

    // 4) layer 3
    gemm_bin<0><<<dim3(HD / 128, MR / 128), blk>>>(a, W3, h, MR, HD, HD, nullptr);
    stats_partial<<<gridStats, blk>>>(h, ps, pq);
    stats_final<<<dim3(HD / 256), blk>>>(ps, pq, mu, rs);
    sign_act<<<gridSign, blk>>>(h, mu, rs, g3, b3, a);

    // 5) layer 4: y = (a @ sgn(W4)^T) * scale, written transposed to (N,F,T)
    gemm_bin<1><<<dim3(FIN / 128, MR / 128), blk>>>(a, W4, y, MR, FIN, HD, scale);
}

// round 3
// speedup vs baseline: 4.6093x; 4.6093x over previous
#include <cuda_runtime.h>
#include <cuda_bf16.h>
#include <cstdint>
#include <cstddef>

#define NB   16
#define FIN  512
#define TD   512
#define MR   8192
#define HD   2048

#define BM   128
#define BN   128
#define BK   32
#define STAGES 4
#define LDAE  40                        // smem row stride in bf16 elems (80 B)
#define TILEB (BM * LDAE * 2)           // 10240 B per matrix tile
#define STAGEB (2 * TILEB)              // 20480 B per stage
#define SMEM_DYN (STAGES * STAGEB)      // 81920 B

// ---------------- scratch ----------------------------------------------------
__device__ __nv_bfloat16 g_xt3[(size_t)MR * 1536];
__device__ __nv_bfloat16 g_w1b[(size_t)HD * 1536];
__device__ __nv_bfloat16 g_w2b[(size_t)HD * HD];
__device__ __nv_bfloat16 g_w3b[(size_t)HD * HD];
__device__ __nv_bfloat16 g_w4b[(size_t)FIN * HD];
__device__ float g_h[(size_t)MR * HD];
__device__ __nv_bfloat16 g_a[(size_t)MR * HD];
__device__ float g_mu[HD], g_rs[HD], g_ps[8 * HD], g_pq[8 * HD];

__device__ __forceinline__ float sgnf(float v) {
    return (v > 0.f) ? 1.f : ((v < 0.f) ? -1.f : 0.f);
}
__device__ __forceinline__ uint32_t smem_u32(const void* p) {
    return (uint32_t)__cvta_generic_to_shared(p);
}
__device__ __forceinline__ void cp16(uint32_t dst, const void* src) {
    asm volatile("cp.async.cg.shared.global [%0], [%1], 16;" :: "r"(dst), "l"(src));
}
__device__ __forceinline__ void ldsm4(uint32_t& r0, uint32_t& r1, uint32_t& r2, uint32_t& r3,
                                      uint32_t a) {
    asm volatile("ldmatrix.sync.aligned.m8n8.x4.shared.b16 {%0,%1,%2,%3}, [%4];"
                 : "=r"(r0), "=r"(r1), "=r"(r2), "=r"(r3) : "r"(a));
}
__device__ __forceinline__ void mma16816(float* c, const uint32_t* a, const uint32_t* b) {
    asm volatile("mma.sync.aligned.m16n8k16.row.col.f32.bf16.bf16.f32 "
                 "{%0,%1,%2,%3},{%4,%5,%6,%7},{%8,%9},{%0,%1,%2,%3};"
                 : "+f"(c[0]), "+f"(c[1]), "+f"(c[2]), "+f"(c[3])
                 : "r"(a[0]), "r"(a[1]), "r"(a[2]), "r"(a[3]), "r"(b[0]), "r"(b[1]));
}

// ---------------- tile loader: A(M,K) rows bm..bm+127, B(N,K) rows bn..bn+127 --
__device__ __forceinline__ void load_stage(
    const __nv_bfloat16* __restrict__ A, const __nv_bfloat16* __restrict__ B,
    int K, int bm, int bn, uint32_t smbase, int tid, int stage, int kc)
{
    uint32_t sA = smbase + stage * STAGEB;
    uint32_t sB = sA + TILEB;
    const char* gA = (const char*)(A + (size_t)bm * K + (size_t)kc * BK);
    const char* gB = (const char*)(B + (size_t)bn * K + (size_t)kc * BK);
    size_t rowb = (size_t)K * 2;
#pragma unroll
    for (int i = 0; i < 2; i++) {
        int idx = tid + i * 256;        // 0..511
        int r = idx >> 2, c = idx & 3;  // row 0..127, 16B chunk 0..3
        cp16(sA + r * 80 + c * 16, gA + (size_t)r * rowb + c * 16);
    }
#pragma unroll
    for (int i = 0; i < 2; i++) {
        int idx = tid + i * 256;
        int r = idx >> 2, c = idx & 3;
        cp16(sB + r * 80 + c * 16, gB + (size_t)r * rowb + c * 16);
    }
    asm volatile("cp.async.commit_group;" ::: "memory");
}

// ---------------- HMMA GEMM: C[m,n] = sum_k A[m,k]*B[n,k] --------------------
// EPI 0: C row-major (M,N) fp32.  EPI 1: y[batch, n, t] = acc*scale[n], m=batch*TD+t
template <int EPI>
__global__ void __launch_bounds__(256, 2)
gemm_tc(const __nv_bfloat16* __restrict__ A, const __nv_bfloat16* __restrict__ B,
        float* __restrict__ C, int N, int K, const float* __restrict__ scale)
{
    extern __shared__ char smraw[];
    const uint32_t smbase = smem_u32(smraw);
    const int tid = threadIdx.x, wid = tid >> 5, lid = tid & 31;
    const int bm = blockIdx.y * BM, bn = blockIdx.x * BN;
    const int NC = K / BK;
    const int wm = (wid & 1) * 64;   // warp M offset in tile
    const int wn = (wid >> 1) * 32;  // warp N offset in tile

    // ldmatrix lane mapping (x4): row within 16, col within 16 (elems)
    const int lr = ((lid >> 3) & 1) * 8 + (lid & 7);
    const int lc = (lid >> 4) * 8;

    float acc[4][4][4];
#pragma unroll
    for (int i = 0; i < 4; i++)
#pragma unroll
        for (int j = 0; j < 4; j++)
#pragma unroll
            for (int q = 0; q < 4; q++) acc[i][j][q] = 0.f;

    // prologue
#pragma unroll
    for (int pc = 0; pc < STAGES - 1; ++pc)
        load_stage(A, B, K, bm, bn, smbase, tid, pc, pc);

    for (int kc = 0; kc < NC; ++kc) {
        const int st = kc & (STAGES - 1);
        asm volatile("cp.async.wait_group %0;" :: "n"(STAGES - 2) : "memory");
        __syncthreads();

        const uint32_t aBase = smbase + st * STAGEB;
        const uint32_t bBase = aBase + TILEB;
#pragma unroll
        for (int ks = 0; ks < 2; ++ks) {
            uint32_t a[4][4];
#pragma unroll
            for (int i = 0; i < 4; i++) {
                uint32_t addr = aBase + (uint32_t)(wm + i * 16 + lr) * 80
                              + (uint32_t)(ks * 16 + lc) * 2;
                ldsm4(a[i][0], a[i][1], a[i][2], a[i][3], addr);
            }
            uint32_t b[4][2];
#pragma unroll
            for (int jj = 0; jj < 2; jj++) {
                uint32_t r0, r1, r2, r3;
                uint32_t addr = bBase + (uint32_t)(wn + jj * 16 + lr) * 80
                              + (uint32_t)(ks * 16 + lc) * 2;
                ldsm4(r0, r1, r2, r3, addr);
                b[jj * 2 + 0][0] = r0; b[jj * 2 + 0][1] = r2;
                b[jj * 2 + 1][0] = r1; b[jj * 2 + 1][1] = r3;
            }
#pragma unroll
            for (int i = 0; i < 4; i++)
#pragma unroll
                for (int j = 0; j < 4; j++)
                    mma16816(acc[i][j], a[i], b[j]);
        }
        int nk = kc + STAGES - 1;
        if (nk < NC)
            load_stage(A, B, K, bm, bn, smbase, tid, nk & (STAGES - 1), nk);
        else
            asm volatile("cp.async.commit_group;" ::: "memory");
    }

    // epilogue: warp tile 64x32; c frag: rows lid/4 (+8), cols (lid%4)*2
    const int row0 = lid >> 2, col0 = (lid & 3) * 2;
    if (EPI == 0) {
#pragma unroll
        for (int i = 0; i < 4; i++) {
#pragma unroll
            for (int j = 0; j < 4; j++) {
                int m0 = bm + wm + i * 16 + row0;
                int n0 = bn + wn + j * 8 + col0;
                *(float2*)&C[(size_t)m0 * N + n0]       = make_float2(acc[i][j][0], acc[i][j][1]);
                *(float2*)&C[(size_t)(m0 + 8) * N + n0] = make_float2(acc[i][j][2], acc[i][j][3]);
            }
        }
    } else {
#pragma unroll
        for (int i = 0; i < 4; i++) {
            int m0 = bm + wm + i * 16 + row0;
            int b0 = m0 / TD, t0 = m0 % TD;          // m0+8 in same batch (TD mult of 16)
#pragma unroll
            for (int j = 0; j < 4; j++) {
                int n0 = bn + wn + j * 8 + col0;
                float s0 = scale[n0], s1 = scale[n0 + 1];
                C[((size_t)b0 * FIN + n0) * TD + t0]         = acc[i][j][0] * s0;
                C[((size_t)b0 * FIN + n0 + 1) * TD + t0]     = acc[i][j][1] * s1;
                C[((size_t)b0 * FIN + n0) * TD + t0 + 8]     = acc[i][j][2] * s0;
                C[((size_t)b0 * FIN + n0 + 1) * TD + t0 + 8] = acc[i][j][3] * s1;
            }
        }
    }
}

// ---------------- prep kernels -------------------------------------------------
__global__ void transpose_split(const float* __restrict__ x, __nv_bfloat16* __restrict__ xt3) {
    __shared__ float tile[32][33];
    int n = blockIdx.z, t0 = blockIdx.x * 32, f0 = blockIdx.y * 32;
    const float* xp = x + (size_t)n * FIN * TD;
#pragma unroll
    for (int i = 0; i < 4; i++) {
        int f = f0 + threadIdx.y + i * 8;
        tile[threadIdx.y + i * 8][threadIdx.x] = xp[(size_t)f * TD + t0 + threadIdx.x];
    }
    __syncthreads();
#pragma unroll
    for (int i = 0; i < 4; i++) {
        int t = t0 + threadIdx.y + i * 8;
        int f = f0 + threadIdx.x;
        float v = tile[threadIdx.x][threadIdx.y + i * 8];
        __nv_bfloat16 hi = __float2bfloat16(v);
        float r1 = v - __bfloat162float(hi);
        __nv_bfloat16 md = __float2bfloat16(r1);
        float r2 = r1 - __bfloat162float(md);
        __nv_bfloat16 lo = __float2bfloat16(r2);
        size_t row = (size_t)((size_t)n * TD + t) * 1536;
        xt3[row + f] = hi;
        xt3[row + 512 + f] = md;
        xt3[row + 1024 + f] = lo;
    }
}

__global__ void binw(const float* __restrict__ W, __nv_bfloat16* __restrict__ o, int n) {
    int i = blockIdx.x * 256 + threadIdx.x;
    if (i < n) o[i] = __float2bfloat16(sgnf(W[i]));
}
__global__ void binw3(const float* __restrict__ W1, __nv_bfloat16* __restrict__ o) {
    int i = blockIdx.x * 256 + threadIdx.x;
    if (i < HD * FIN) {
        int row = i >> 9, k = i & 511;
        __nv_bfloat16 s = __float2bfloat16(sgnf(W1[i]));
        size_t base = (size_t)row * 1536 + k;
        o[base] = s; o[base + 512] = s; o[base + 1024] = s;
    }
}

// ---------------- BN stats (deterministic two-stage) ---------------------------
__global__ void stats_partial(const float* __restrict__ h,
                              float* __restrict__ ps, float* __restrict__ pq) {
    int c = threadIdx.x & 31, lane = threadIdx.x >> 5;
    int col = blockIdx.x * 32 + c;
    int r0 = blockIdx.y * (MR / 8);
    float s = 0.f, sq = 0.f;
    for (int i = lane; i < MR / 8; i += 8) {
        float v = h[(size_t)(r0 + i) * HD + col];
        s += v; sq += v * v;
    }
    __shared__ float ss[8][33], sv[8][33];
    ss[lane][c] = s; sv[lane][c] = sq;
    __syncthreads();
    if (lane == 0) {
        float ts = 0.f, tq = 0.f;
#pragma unroll
        for (int l = 0; l < 8; l++) { ts += ss[l][c]; tq += sv[l][c]; }
        ps[blockIdx.y * HD + col] = ts;
        pq[blockIdx.y * HD + col] = tq;
    }
}
__global__ void stats_final(const float* __restrict__ ps, const float* __restrict__ pq,
                            float* __restrict__ mu, float* __restrict__ rs) {
    int col = blockIdx.x * 256 + threadIdx.x;
    if (col >= HD) return;
    float s = 0.f, sq = 0.f;
#pragma unroll
    for (int p = 0; p < 8; p++) { s += ps[p * HD + col]; sq += pq[p * HD + col]; }
    float m = s * (1.f / MR);
    float var = sq * (1.f / MR) - m * m;
    if (var < 0.f) var = 0.f;
    mu[col] = m;
    rs[col] = rsqrtf(var + 1e-5f);
}

// ---------------- sign activation -> bf16 --------------------------------------
__global__ void sign_act(const float* __restrict__ h,
                         const float* __restrict__ mu, const float* __restrict__ rs,
                         const float* __restrict__ g, const float* __restrict__ b,
                         __nv_bfloat16* __restrict__ a) {
    size_t i4 = (size_t)blockIdx.x * blockDim.x + threadIdx.x;
    size_t e0 = i4 * 4;
    if (e0 >= (size_t)MR * HD) return;
    int j = (int)(e0 % HD);
    float4 hv = *(const float4*)&h[e0];
    float s0 = sgnf(g[j + 0] * (hv.x - mu[j + 0]) * rs[j + 0] + b[j + 0]);
    float s1 = sgnf(g[j + 1] * (hv.y - mu[j + 1]) * rs[j + 1] + b[j + 1]);
    float s2 = sgnf(g[j + 2] * (hv.z - mu[j + 2]) * rs[j + 2] + b[j + 2]);
    float s3 = sgnf(g[j + 3] * (hv.w - mu[j + 3]) * rs[j + 3] + b[j + 3]);
    __nv_bfloat162 p0, p1;
    p0.x = __float2bfloat16(s0); p0.y = __float2bfloat16(s1);
    p1.x = __float2bfloat16(s2); p1.y = __float2bfloat16(s3);
    *(__nv_bfloat162*)&a[e0] = p0;
    *(__nv_bfloat162*)&a[e0 + 2] = p1;
}

// ---------------- host orchestration -------------------------------------------
extern "C" void kernel_launch(void* const* d_in, const int* in_sizes, int n_in,
                              void* d_out, int out_size) {
    const float* x     = (const float*)d_in[0];
    const float* W1    = (const float*)d_in[2];
    const float* g1    = (const float*)d_in[3];
    const float* b1    = (const float*)d_in[4];
    const float* W2    = (const float*)d_in[5];
    const float* g2    = (const float*)d_in[6];
    const float* b2    = (const float*)d_in[7];
    const float* W3    = (const float*)d_in[8];
    const float* g3    = (const float*)d_in[9];
    const float* b3    = (const float*)d_in[10];
    const float* W4    = (const float*)d_in[11];
    const float* scale = (const float*)d_in[12];
    float* y = (float*)d_out;

    __nv_bfloat16 *xt3, *w1b, *w2b, *w3b, *w4b, *a;
    float *h, *mu, *rs, *ps, *pq;
    cudaGetSymbolAddress((void**)&xt3, g_xt3);
    cudaGetSymbolAddress((void**)&w1b, g_w1b);
    cudaGetSymbolAddress((void**)&w2b, g_w2b);
    cudaGetSymbolAddress((void**)&w3b, g_w3b);
    cudaGetSymbolAddress((void**)&w4b, g_w4b);
    cudaGetSymbolAddress((void**)&h,   g_h);
    cudaGetSymbolAddress((void**)&a,   g_a);
    cudaGetSymbolAddress((void**)&mu,  g_mu);
    cudaGetSymbolAddress((void**)&rs,  g_rs);
    cudaGetSymbolAddress((void**)&ps,  g_ps);
    cudaGetSymbolAddress((void**)&pq,  g_pq);

    cudaFuncSetAttribute(gemm_tc<0>, cudaFuncAttributeMaxDynamicSharedMemorySize, SMEM_DYN);
    cudaFuncSetAttribute(gemm_tc<1>, cudaFuncAttributeMaxDynamicSharedMemorySize, SMEM_DYN);

    // prep
    transpose_split<<<dim3(TD / 32, FIN / 32, NB), dim3(32, 8)>>>(x, xt3);
    binw3<<<(HD * FIN + 255) / 256, 256>>>(W1, w1b);
    binw<<<(HD * HD + 255) / 256, 256>>>(W2, w2b, HD * HD);
    binw<<<(HD * HD + 255) / 256, 256>>>(W3, w3b, HD * HD);
    binw<<<(FIN * HD + 255) / 256, 256>>>(W4, w4b, FIN * HD);

    dim3 blk(256);
    dim3 gridStats(HD / 32, 8);
    dim3 gridSign((unsigned)(((size_t)MR * HD / 4 + 255) / 256));
    dim3 gGemm(HD / BN, MR / BM);   // (16, 64)
    dim3 gGemm4(FIN / BN, MR / BM); // (4, 64)

    // layer 1: h = [hi|mid|lo] @ [sgnW1|sgnW1|sgnW1]^T  (K=1536)
    gemm_tc<0><<<gGemm, blk, SMEM_DYN>>>(xt3, w1b, h, HD, 1536, nullptr);
    stats_partial<<<gridStats, blk>>>(h, ps, pq);
    stats_final<<<dim3(HD / 256), blk>>>(ps, pq, mu, rs);
    sign_act<<<gridSign, blk>>>(h, mu, rs, g1, b1, a);

    // layer 2
    gemm_tc<0><<<gGemm, blk, SMEM_DYN>>>(a, w2b, h, HD, HD, nullptr);
    stats_partial<<<gridStats, blk>>>(h, ps, pq);
    stats_final<<<dim3(HD / 256), blk>>>(ps, pq, mu, rs);
    sign_act<<<gridSign, blk>>>(h, mu, rs, g2, b2, a);

    // layer 3
    gemm_tc<0><<<gGemm, blk, SMEM_DYN>>>(a, w3b, h, HD, HD, nullptr);
    stats_partial<<<gridStats, blk>>>(h, ps, pq);
    stats_final<<<dim3(HD / 256), blk>>>(ps, pq, mu, rs);
    sign_act<<<gridSign, blk>>>(h, mu, rs, g3, b3, a);

    // layer 4: y = (a @ sgnW4^T) * scale, transposed store to (N,F,T)
    gemm_tc<1><<<gGemm4, blk, SMEM_DYN>>>(a, w4b, y, FIN, HD, scale);
}